// round 12
// baseline (speedup 1.0000x reference)
#include <cuda_runtime.h>
#include <cstdint>

// ---------------------------------------------------------------------------
// Static device scratch (graph-safe; no runtime allocations).
//   N = 100000 <= 131072, E = 1250000. Fixed-capacity buckets: 64 edges/node.
//   P(Binomial(1.25M, 1e-5) > 64) ~ 1e-30  => capacity never binds (clamped).
// ---------------------------------------------------------------------------
#define SLOTS 131072
#define CAP   64
__device__ int  g_cnt[SLOTS];            // per-node in-degree / bucket cursor
__device__ int2 g_edges[SLOTS * CAP];    // bucket payload: (edge_id, src_idx)

// ---------------------------------------------------------------------------
// K1: zero the counters (int4 stores, 2 per thread).
// ---------------------------------------------------------------------------
__global__ void zero_kernel() {
    int i = blockIdx.x * blockDim.x + threadIdx.x;
    int4* p = (int4*)g_cnt;
    int4 z = make_int4(0, 0, 0, 0);
    p[i * 2 + 0] = z;
    p[i * 2 + 1] = z;
}

// ---------------------------------------------------------------------------
// K2: single-pass bucket scatter. 8 edges per thread (2x int4 loads of each
// index array) -> 8 independent atomic->store chains for latency overlap.
// ---------------------------------------------------------------------------
__global__ void scatter_kernel(const int4* __restrict__ src4,
                               const int4* __restrict__ dst4, int E4, int N) {
    int i = blockIdx.x * blockDim.x + threadIdx.x;   // processes int4 pair i
    int i0 = i * 2;
    int i1 = i * 2 + 1;
    if (i0 >= E4) return;

    int4 s0 = src4[i0];
    int4 d0 = dst4[i0];
    int e0 = i0 * 4;

    {
        int d = min(max(d0.x, 0), N - 1);
        int p = atomicAdd(&g_cnt[d], 1);
        if (p < CAP) g_edges[d * CAP + p] = make_int2(e0 + 0, min(max(s0.x, 0), N - 1));
    }
    {
        int d = min(max(d0.y, 0), N - 1);
        int p = atomicAdd(&g_cnt[d], 1);
        if (p < CAP) g_edges[d * CAP + p] = make_int2(e0 + 1, min(max(s0.y, 0), N - 1));
    }
    {
        int d = min(max(d0.z, 0), N - 1);
        int p = atomicAdd(&g_cnt[d], 1);
        if (p < CAP) g_edges[d * CAP + p] = make_int2(e0 + 2, min(max(s0.z, 0), N - 1));
    }
    {
        int d = min(max(d0.w, 0), N - 1);
        int p = atomicAdd(&g_cnt[d], 1);
        if (p < CAP) g_edges[d * CAP + p] = make_int2(e0 + 3, min(max(s0.w, 0), N - 1));
    }

    if (i1 >= E4) return;
    int4 s1 = src4[i1];
    int4 d1 = dst4[i1];
    int e1 = i1 * 4;

    {
        int d = min(max(d1.x, 0), N - 1);
        int p = atomicAdd(&g_cnt[d], 1);
        if (p < CAP) g_edges[d * CAP + p] = make_int2(e1 + 0, min(max(s1.x, 0), N - 1));
    }
    {
        int d = min(max(d1.y, 0), N - 1);
        int p = atomicAdd(&g_cnt[d], 1);
        if (p < CAP) g_edges[d * CAP + p] = make_int2(e1 + 1, min(max(s1.y, 0), N - 1));
    }
    {
        int d = min(max(d1.z, 0), N - 1);
        int p = atomicAdd(&g_cnt[d], 1);
        if (p < CAP) g_edges[d * CAP + p] = make_int2(e1 + 2, min(max(s1.z, 0), N - 1));
    }
    {
        int d = min(max(d1.w, 0), N - 1);
        int p = atomicAdd(&g_cnt[d], 1);
        if (p < CAP) g_edges[d * CAP + p] = make_int2(e1 + 3, min(max(s1.w, 0), N - 1));
    }
}

// ---------------------------------------------------------------------------
// K3: gather + mean. 16 lanes per node; each lane owns one float4 of the
// 64 features. Main loop consumes 4 edges per iteration via two int4 bucket
// loads -> 8 independent 16B row loads per iteration (unroll 2 => ~16 loads
// in flight). 2-edge and 1-edge tails. Divide fused; one clean store per row.
// ---------------------------------------------------------------------------
__global__ void gather_kernel(const float4* __restrict__ src_emb,
                              const float4* __restrict__ edge_emb,
                              float4* __restrict__ out, int N) {
    int gtid = blockIdx.x * blockDim.x + threadIdx.x;
    int node = gtid >> 4;
    int lane = gtid & 15;
    if (node >= N) return;

    int cnt = g_cnt[node];
    int m   = min(cnt, CAP);
    const int4* b4 = (const int4*)&g_edges[node * CAP];  // 512B-aligned base

    float4 acc = make_float4(0.f, 0.f, 0.f, 0.f);
    int j = 0;
    #pragma unroll 2
    for (; j + 4 <= m; j += 4) {
        int4 ea = __ldg(&b4[(j >> 1) + 0]);   // edges j, j+1
        int4 eb = __ldg(&b4[(j >> 1) + 1]);   // edges j+2, j+3
        float4 a0 = edge_emb[(size_t)ea.x * 16 + lane];
        float4 b0 = src_emb [(size_t)ea.y * 16 + lane];
        float4 a1 = edge_emb[(size_t)ea.z * 16 + lane];
        float4 b1 = src_emb [(size_t)ea.w * 16 + lane];
        float4 a2 = edge_emb[(size_t)eb.x * 16 + lane];
        float4 b2 = src_emb [(size_t)eb.y * 16 + lane];
        float4 a3 = edge_emb[(size_t)eb.z * 16 + lane];
        float4 b3 = src_emb [(size_t)eb.w * 16 + lane];
        acc.x += (a0.x + b0.x) + (a1.x + b1.x) + (a2.x + b2.x) + (a3.x + b3.x);
        acc.y += (a0.y + b0.y) + (a1.y + b1.y) + (a2.y + b2.y) + (a3.y + b3.y);
        acc.z += (a0.z + b0.z) + (a1.z + b1.z) + (a2.z + b2.z) + (a3.z + b3.z);
        acc.w += (a0.w + b0.w) + (a1.w + b1.w) + (a2.w + b2.w) + (a3.w + b3.w);
    }
    if (j + 2 <= m) {
        int4 ea = __ldg(&b4[j >> 1]);
        float4 a0 = edge_emb[(size_t)ea.x * 16 + lane];
        float4 b0 = src_emb [(size_t)ea.y * 16 + lane];
        float4 a1 = edge_emb[(size_t)ea.z * 16 + lane];
        float4 b1 = src_emb [(size_t)ea.w * 16 + lane];
        acc.x += (a0.x + b0.x) + (a1.x + b1.x);
        acc.y += (a0.y + b0.y) + (a1.y + b1.y);
        acc.z += (a0.z + b0.z) + (a1.z + b1.z);
        acc.w += (a0.w + b0.w) + (a1.w + b1.w);
        j += 2;
    }
    if (j < m) {
        int2 ee = __ldg(&g_edges[node * CAP + j]);
        float4 a = edge_emb[(size_t)ee.x * 16 + lane];
        float4 b = src_emb [(size_t)ee.y * 16 + lane];
        acc.x += a.x + b.x;
        acc.y += a.y + b.y;
        acc.z += a.z + b.z;
        acc.w += a.w + b.w;
    }

    float inv = (cnt > 0) ? (1.0f / (float)cnt) : 0.0f;
    out[(size_t)node * 16 + lane] =
        make_float4(acc.x * inv, acc.y * inv, acc.z * inv, acc.w * inv);
}

// ---------------------------------------------------------------------------
// Launch. Inputs (metadata order):
//   d_in[0] src_embedding  float32 [N,64]
//   d_in[1] edge_embedding float32 [E,64]
//   d_in[2] src_idx        int32   [E]
//   d_in[3] dst_idx        int32   [E]
//   d_in[4] num_nodes      (unused; N derived from in_sizes[0])
// Output: float32 [N,64]
// ---------------------------------------------------------------------------
extern "C" void kernel_launch(void* const* d_in, const int* in_sizes, int n_in,
                              void* d_out, int out_size) {
    const float* src_emb  = (const float*)d_in[0];
    const float* edge_emb = (const float*)d_in[1];
    const int*   src_idx  = (const int*)d_in[2];
    const int*   dst_idx  = (const int*)d_in[3];
    float*       out      = (float*)d_out;

    const int D = 64;
    int N  = in_sizes[0] / D;
    int E  = in_sizes[2];
    int E4 = E / 4;                      // E = 1.25M divisible by 4

    // K1: SLOTS ints = SLOTS/4 int4s, 2 per thread
    zero_kernel<<<SLOTS / 4 / 2 / 256, 256>>>();

    // K2: 8 edges (2 int4 pairs) per thread
    int sthreads = (E4 + 1) / 2;
    scatter_kernel<<<(sthreads + 255) / 256, 256>>>((const int4*)src_idx,
                                                    (const int4*)dst_idx, E4, N);

    // K3: 16 threads per node
    long long gthreads = (long long)N * 16;
    gather_kernel<<<(int)((gthreads + 255) / 256), 256>>>(
        (const float4*)src_emb, (const float4*)edge_emb, (float4*)out, N);
}

// round 14
// speedup vs baseline: 1.1020x; 1.1020x over previous
#include <cuda_runtime.h>
#include <cstdint>

// ---------------------------------------------------------------------------
// Static device scratch (graph-safe; no runtime allocations).
//   N = 100000 <= 131072, E = 1250000. Fixed-capacity buckets: 64 edges/node.
//   P(Binomial(1.25M, 1e-5) > 64) ~ 1e-30  => capacity never binds (clamped).
//
// g_cnt lifecycle: zero-initialized at module load; scatter increments it;
// gather consumes it and resets it to zero in its epilogue. Slots >= N are
// never incremented (dst is clamped), so every launch starts from all-zeros
// without a dedicated zeroing kernel.
// ---------------------------------------------------------------------------
#define SLOTS 131072
#define CAP   64
__device__ int  g_cnt[SLOTS];            // per-node in-degree / bucket cursor
__device__ int2 g_edges[SLOTS * CAP];    // bucket payload: (edge_id, src_idx)

// ---------------------------------------------------------------------------
// K1: single-pass bucket scatter. int4-vectorized index loads: 4 edges per
// thread, 4 independent atomic->store chains for latency overlap.
// ---------------------------------------------------------------------------
__global__ void scatter_kernel(const int4* __restrict__ src4,
                               const int4* __restrict__ dst4, int E4, int N) {
    int i = blockIdx.x * blockDim.x + threadIdx.x;
    if (i >= E4) return;
    int4 s = src4[i];
    int4 d = dst4[i];
    int e = i * 4;

    int d0 = min(max(d.x, 0), N - 1);
    int p0 = atomicAdd(&g_cnt[d0], 1);
    if (p0 < CAP) g_edges[d0 * CAP + p0] = make_int2(e + 0, min(max(s.x, 0), N - 1));

    int d1 = min(max(d.y, 0), N - 1);
    int p1 = atomicAdd(&g_cnt[d1], 1);
    if (p1 < CAP) g_edges[d1 * CAP + p1] = make_int2(e + 1, min(max(s.y, 0), N - 1));

    int d2 = min(max(d.z, 0), N - 1);
    int p2 = atomicAdd(&g_cnt[d2], 1);
    if (p2 < CAP) g_edges[d2 * CAP + p2] = make_int2(e + 2, min(max(s.z, 0), N - 1));

    int d3 = min(max(d.w, 0), N - 1);
    int p3 = atomicAdd(&g_cnt[d3], 1);
    if (p3 < CAP) g_edges[d3 * CAP + p3] = make_int2(e + 3, min(max(s.w, 0), N - 1));
}

// ---------------------------------------------------------------------------
// K2: gather + mean. 16 lanes per node; each lane owns one float4 of the
// 64 features. Consumes 2 edges per iteration via a single int4 bucket load
// (bucket base is 512B-aligned), giving 4 independent 16B row loads per
// iteration; unroll 2 keeps ~8 loads in flight. Divide fused; single store.
// Epilogue: lane 0 resets g_cnt[node] for the next launch/replay.
// ---------------------------------------------------------------------------
__global__ void gather_kernel(const float4* __restrict__ src_emb,
                              const float4* __restrict__ edge_emb,
                              float4* __restrict__ out, int N) {
    int gtid = blockIdx.x * blockDim.x + threadIdx.x;
    int node = gtid >> 4;
    int lane = gtid & 15;
    if (node >= N) return;

    int cnt = g_cnt[node];
    int m   = min(cnt, CAP);
    const int2* bucket = &g_edges[node * CAP];

    float4 acc = make_float4(0.f, 0.f, 0.f, 0.f);
    int j = 0;
    #pragma unroll 2
    for (; j + 2 <= m; j += 2) {
        int4 ee = __ldg((const int4*)(bucket + j));   // 2 edges, broadcast
        float4 a0 = edge_emb[(size_t)ee.x * 16 + lane];
        float4 b0 = src_emb [(size_t)ee.y * 16 + lane];
        float4 a1 = edge_emb[(size_t)ee.z * 16 + lane];
        float4 b1 = src_emb [(size_t)ee.w * 16 + lane];
        acc.x += (a0.x + b0.x) + (a1.x + b1.x);
        acc.y += (a0.y + b0.y) + (a1.y + b1.y);
        acc.z += (a0.z + b0.z) + (a1.z + b1.z);
        acc.w += (a0.w + b0.w) + (a1.w + b1.w);
    }
    if (j < m) {
        int2 ee = __ldg(bucket + j);
        float4 a = edge_emb[(size_t)ee.x * 16 + lane];
        float4 b = src_emb [(size_t)ee.y * 16 + lane];
        acc.x += a.x + b.x;
        acc.y += a.y + b.y;
        acc.z += a.z + b.z;
        acc.w += a.w + b.w;
    }

    float inv = (cnt > 0) ? (1.0f / (float)cnt) : 0.0f;
    out[(size_t)node * 16 + lane] =
        make_float4(acc.x * inv, acc.y * inv, acc.z * inv, acc.w * inv);

    // Reset the counter for the next launch (replaces the zero kernel).
    if (lane == 0 && cnt != 0) g_cnt[node] = 0;
}

// ---------------------------------------------------------------------------
// Launch. Inputs (metadata order):
//   d_in[0] src_embedding  float32 [N,64]
//   d_in[1] edge_embedding float32 [E,64]
//   d_in[2] src_idx        int32   [E]
//   d_in[3] dst_idx        int32   [E]
//   d_in[4] num_nodes      (unused; N derived from in_sizes[0])
// Output: float32 [N,64]
// ---------------------------------------------------------------------------
extern "C" void kernel_launch(void* const* d_in, const int* in_sizes, int n_in,
                              void* d_out, int out_size) {
    const float* src_emb  = (const float*)d_in[0];
    const float* edge_emb = (const float*)d_in[1];
    const int*   src_idx  = (const int*)d_in[2];
    const int*   dst_idx  = (const int*)d_in[3];
    float*       out      = (float*)d_out;

    const int D = 64;
    int N  = in_sizes[0] / D;
    int E  = in_sizes[2];
    int E4 = E / 4;                      // E = 1.25M divisible by 4

    scatter_kernel<<<(E4 + 255) / 256, 256>>>((const int4*)src_idx,
                                              (const int4*)dst_idx, E4, N);

    long long gthreads = (long long)N * 16;
    gather_kernel<<<(int)((gthreads + 255) / 256), 256>>>(
        (const float4*)src_emb, (const float4*)edge_emb, (float4*)out, N);
}

// round 15
// speedup vs baseline: 1.1758x; 1.0670x over previous
#include <cuda_runtime.h>
#include <cstdint>

// ---------------------------------------------------------------------------
// Static device scratch (graph-safe; no runtime allocations).
//   N = 100000 <= 131072, E = 1250000. Fixed-capacity buckets: 64 edges/node.
//   P(Binomial(1.25M, 1e-5) > 64) ~ 1e-30  => capacity never binds (clamped).
//
// g_cnt lifecycle: zero-initialized at module load; scatter increments it;
// gather consumes it and resets it in its epilogue. Slots >= N are never
// incremented (dst clamped), so every launch starts from all-zeros without a
// dedicated zeroing kernel.
// ---------------------------------------------------------------------------
#define SLOTS 131072
#define CAP   64
__device__ int  g_cnt[SLOTS];            // per-node in-degree / bucket cursor
__device__ int2 g_edges[SLOTS * CAP];    // bucket payload: (edge_id, src_idx)

// ---------------------------------------------------------------------------
// K1: single-pass bucket scatter. Grid-stride loop: each thread handles 2
// COALESCED int4 loads (8 edges, 8 independent atomic->store chains in
// flight). Adjacent threads read adjacent int4s within each iteration.
// ---------------------------------------------------------------------------
__global__ void scatter_kernel(const int4* __restrict__ src4,
                               const int4* __restrict__ dst4, int E4, int N) {
    int stride = gridDim.x * blockDim.x;
    for (int i = blockIdx.x * blockDim.x + threadIdx.x; i < E4; i += stride) {
        int4 s = src4[i];
        int4 d = dst4[i];
        int e = i * 4;

        int d0 = min(max(d.x, 0), N - 1);
        int p0 = atomicAdd(&g_cnt[d0], 1);
        if (p0 < CAP) g_edges[d0 * CAP + p0] = make_int2(e + 0, min(max(s.x, 0), N - 1));

        int d1 = min(max(d.y, 0), N - 1);
        int p1 = atomicAdd(&g_cnt[d1], 1);
        if (p1 < CAP) g_edges[d1 * CAP + p1] = make_int2(e + 1, min(max(s.y, 0), N - 1));

        int d2 = min(max(d.z, 0), N - 1);
        int p2 = atomicAdd(&g_cnt[d2], 1);
        if (p2 < CAP) g_edges[d2 * CAP + p2] = make_int2(e + 2, min(max(s.z, 0), N - 1));

        int d3 = min(max(d.w, 0), N - 1);
        int p3 = atomicAdd(&g_cnt[d3], 1);
        if (p3 < CAP) g_edges[d3 * CAP + p3] = make_int2(e + 3, min(max(s.w, 0), N - 1));
    }
}

// ---------------------------------------------------------------------------
// K2: gather + mean. 16 lanes per node; each lane owns one float4 of the
// 64 features. 2 edges per iteration via one int4 bucket load, with the NEXT
// iteration's int4 software-prefetched so index latency overlaps row loads.
// Divide fused; single store per row. Epilogue resets g_cnt[node].
// ---------------------------------------------------------------------------
__global__ void gather_kernel(const float4* __restrict__ src_emb,
                              const float4* __restrict__ edge_emb,
                              float4* __restrict__ out, int N) {
    int gtid = blockIdx.x * blockDim.x + threadIdx.x;
    int node = gtid >> 4;
    int lane = gtid & 15;
    if (node >= N) return;

    int cnt = g_cnt[node];
    int m   = min(cnt, CAP);
    const int4* b4 = (const int4*)&g_edges[node * CAP];   // 512B-aligned

    float4 acc = make_float4(0.f, 0.f, 0.f, 0.f);
    int j = 0;
    int4 ee_next = (m >= 2) ? __ldg(&b4[0]) : make_int4(0, 0, 0, 0);
    #pragma unroll 2
    for (; j + 2 <= m; j += 2) {
        int4 ee = ee_next;
        if (j + 4 <= m) ee_next = __ldg(&b4[(j >> 1) + 1]);   // prefetch
        float4 a0 = edge_emb[(size_t)ee.x * 16 + lane];
        float4 b0 = src_emb [(size_t)ee.y * 16 + lane];
        float4 a1 = edge_emb[(size_t)ee.z * 16 + lane];
        float4 b1 = src_emb [(size_t)ee.w * 16 + lane];
        acc.x += (a0.x + b0.x) + (a1.x + b1.x);
        acc.y += (a0.y + b0.y) + (a1.y + b1.y);
        acc.z += (a0.z + b0.z) + (a1.z + b1.z);
        acc.w += (a0.w + b0.w) + (a1.w + b1.w);
    }
    if (j < m) {
        int2 ee = __ldg(&g_edges[node * CAP + j]);
        float4 a = edge_emb[(size_t)ee.x * 16 + lane];
        float4 b = src_emb [(size_t)ee.y * 16 + lane];
        acc.x += a.x + b.x;
        acc.y += a.y + b.y;
        acc.z += a.z + b.z;
        acc.w += a.w + b.w;
    }

    float inv = (cnt > 0) ? (1.0f / (float)cnt) : 0.0f;
    out[(size_t)node * 16 + lane] =
        make_float4(acc.x * inv, acc.y * inv, acc.z * inv, acc.w * inv);

    // Reset the counter for the next launch (replaces a zero kernel).
    if (lane == 0 && cnt != 0) g_cnt[node] = 0;
}

// ---------------------------------------------------------------------------
// Launch. Inputs (metadata order):
//   d_in[0] src_embedding  float32 [N,64]
//   d_in[1] edge_embedding float32 [E,64]
//   d_in[2] src_idx        int32   [E]
//   d_in[3] dst_idx        int32   [E]
//   d_in[4] num_nodes      (unused; N derived from in_sizes[0])
// Output: float32 [N,64]
// ---------------------------------------------------------------------------
extern "C" void kernel_launch(void* const* d_in, const int* in_sizes, int n_in,
                              void* d_out, int out_size) {
    const float* src_emb  = (const float*)d_in[0];
    const float* edge_emb = (const float*)d_in[1];
    const int*   src_idx  = (const int*)d_in[2];
    const int*   dst_idx  = (const int*)d_in[3];
    float*       out      = (float*)d_out;

    const int D = 64;
    int N  = in_sizes[0] / D;
    int E  = in_sizes[2];
    int E4 = E / 4;                      // E = 1.25M divisible by 4

    // K1: half as many threads as int4s -> each thread does ~2 coalesced iters
    int sthreads = (E4 + 1) / 2;
    scatter_kernel<<<(sthreads + 255) / 256, 256>>>((const int4*)src_idx,
                                                    (const int4*)dst_idx, E4, N);

    // K2: 16 threads per node, 128-thread blocks for finer scheduling
    long long gthreads = (long long)N * 16;
    gather_kernel<<<(int)((gthreads + 127) / 128), 128>>>(
        (const float4*)src_emb, (const float4*)edge_emb, (float4*)out, N);
}

// round 17
// speedup vs baseline: 1.1937x; 1.0152x over previous
#include <cuda_runtime.h>
#include <cstdint>

// ---------------------------------------------------------------------------
// Static device scratch (graph-safe; no runtime allocations).
//   N = 100000 <= 131072, E = 1250000. Fixed-capacity buckets: 64 edges/node.
//   P(Binomial(1.25M, 1e-5) > 64) ~ 1e-30  => capacity never binds (clamped).
//
// g_cnt lifecycle: zero-initialized at module load; scatter increments it;
// gather consumes it and resets it in its epilogue. Slots >= N are never
// incremented (dst clamped), so every launch starts from all-zeros without a
// dedicated zeroing kernel.
// ---------------------------------------------------------------------------
#define SLOTS 131072
#define CAP   64
__device__ int  g_cnt[SLOTS];            // per-node in-degree / bucket cursor
__device__ int2 g_edges[SLOTS * CAP];    // bucket payload: (edge_id, src_idx)

// ---------------------------------------------------------------------------
// K1: single-pass bucket scatter. Grid-stride loop: each thread handles 2
// COALESCED int4 loads (8 edges, 8 independent atomic->store chains in
// flight). Adjacent threads read adjacent int4s within each iteration.
// ---------------------------------------------------------------------------
__global__ void scatter_kernel(const int4* __restrict__ src4,
                               const int4* __restrict__ dst4, int E4, int N) {
    int stride = gridDim.x * blockDim.x;
    for (int i = blockIdx.x * blockDim.x + threadIdx.x; i < E4; i += stride) {
        int4 s = src4[i];
        int4 d = dst4[i];
        int e = i * 4;

        int d0 = min(max(d.x, 0), N - 1);
        int p0 = atomicAdd(&g_cnt[d0], 1);
        if (p0 < CAP) g_edges[d0 * CAP + p0] = make_int2(e + 0, min(max(s.x, 0), N - 1));

        int d1 = min(max(d.y, 0), N - 1);
        int p1 = atomicAdd(&g_cnt[d1], 1);
        if (p1 < CAP) g_edges[d1 * CAP + p1] = make_int2(e + 1, min(max(s.y, 0), N - 1));

        int d2 = min(max(d.z, 0), N - 1);
        int p2 = atomicAdd(&g_cnt[d2], 1);
        if (p2 < CAP) g_edges[d2 * CAP + p2] = make_int2(e + 2, min(max(s.z, 0), N - 1));

        int d3 = min(max(d.w, 0), N - 1);
        int p3 = atomicAdd(&g_cnt[d3], 1);
        if (p3 < CAP) g_edges[d3 * CAP + p3] = make_int2(e + 3, min(max(s.w, 0), N - 1));
    }
}

// ---------------------------------------------------------------------------
// K2: gather + mean. 16 lanes per node; each lane owns one float4 of the
// 64 features. 2 edges per iteration via one int4 bucket load, next index
// int4 software-prefetched. Cache policy: edge_emb rows are read exactly
// once -> __ldcs (evict-first) so they don't thrash the L2 residency of
// src_emb (reused ~12.5x) and the buckets; output is write-once -> __stcs.
// __launch_bounds__(128, 16) caps regs at 32 -> 100% occupancy ceiling.
// Epilogue: lane 0 resets g_cnt[node] for the next launch/replay.
// ---------------------------------------------------------------------------
__global__ void __launch_bounds__(128, 16)
gather_kernel(const float4* __restrict__ src_emb,
              const float4* __restrict__ edge_emb,
              float4* __restrict__ out, int N) {
    int gtid = blockIdx.x * blockDim.x + threadIdx.x;
    int node = gtid >> 4;
    int lane = gtid & 15;
    if (node >= N) return;

    int cnt = g_cnt[node];
    int m   = min(cnt, CAP);
    const int4* b4 = (const int4*)&g_edges[node * CAP];   // 512B-aligned

    float4 acc = make_float4(0.f, 0.f, 0.f, 0.f);
    int j = 0;
    int4 ee_next = (m >= 2) ? __ldg(&b4[0]) : make_int4(0, 0, 0, 0);
    #pragma unroll 2
    for (; j + 2 <= m; j += 2) {
        int4 ee = ee_next;
        if (j + 4 <= m) ee_next = __ldg(&b4[(j >> 1) + 1]);   // prefetch
        float4 a0 = __ldcs(&edge_emb[(size_t)ee.x * 16 + lane]);
        float4 b0 = __ldg (&src_emb [(size_t)ee.y * 16 + lane]);
        float4 a1 = __ldcs(&edge_emb[(size_t)ee.z * 16 + lane]);
        float4 b1 = __ldg (&src_emb [(size_t)ee.w * 16 + lane]);
        acc.x += (a0.x + b0.x) + (a1.x + b1.x);
        acc.y += (a0.y + b0.y) + (a1.y + b1.y);
        acc.z += (a0.z + b0.z) + (a1.z + b1.z);
        acc.w += (a0.w + b0.w) + (a1.w + b1.w);
    }
    if (j < m) {
        int2 ee = __ldg(&g_edges[node * CAP + j]);
        float4 a = __ldcs(&edge_emb[(size_t)ee.x * 16 + lane]);
        float4 b = __ldg (&src_emb [(size_t)ee.y * 16 + lane]);
        acc.x += a.x + b.x;
        acc.y += a.y + b.y;
        acc.z += a.z + b.z;
        acc.w += a.w + b.w;
    }

    float inv = (cnt > 0) ? (1.0f / (float)cnt) : 0.0f;
    float4 r = make_float4(acc.x * inv, acc.y * inv, acc.z * inv, acc.w * inv);
    __stcs(&out[(size_t)node * 16 + lane], r);

    // Reset the counter for the next launch (replaces a zero kernel).
    if (lane == 0 && cnt != 0) g_cnt[node] = 0;
}

// ---------------------------------------------------------------------------
// Launch. Inputs (metadata order):
//   d_in[0] src_embedding  float32 [N,64]
//   d_in[1] edge_embedding float32 [E,64]
//   d_in[2] src_idx        int32   [E]
//   d_in[3] dst_idx        int32   [E]
//   d_in[4] num_nodes      (unused; N derived from in_sizes[0])
// Output: float32 [N,64]
// ---------------------------------------------------------------------------
extern "C" void kernel_launch(void* const* d_in, const int* in_sizes, int n_in,
                              void* d_out, int out_size) {
    const float* src_emb  = (const float*)d_in[0];
    const float* edge_emb = (const float*)d_in[1];
    const int*   src_idx  = (const int*)d_in[2];
    const int*   dst_idx  = (const int*)d_in[3];
    float*       out      = (float*)d_out;

    const int D = 64;
    int N  = in_sizes[0] / D;
    int E  = in_sizes[2];
    int E4 = E / 4;                      // E = 1.25M divisible by 4

    // K1: half as many threads as int4s -> each thread does ~2 coalesced iters
    int sthreads = (E4 + 1) / 2;
    scatter_kernel<<<(sthreads + 255) / 256, 256>>>((const int4*)src_idx,
                                                    (const int4*)dst_idx, E4, N);

    // K2: 16 threads per node, 128-thread blocks
    long long gthreads = (long long)N * 16;
    gather_kernel<<<(int)((gthreads + 127) / 128), 128>>>(
        (const float4*)src_emb, (const float4*)edge_emb, (float4*)out, N);
}